// round 5
// baseline (speedup 1.0000x reference)
#include <cuda_runtime.h>

#define BB 2
#define L 384
#define D 256
#define H 8
#define DH 32
#define BL (BB*L)
#define INVS 0.17677669529663687f   // 1/sqrt(32)

// ---------------- scratch (static device globals; no allocations) ----------------
__device__ float g_kproj[BB*H*L*DH];   // [b][h][l][dh]
__device__ float g_qu[BB*H*L*DH];      // (q+u)*INVS, [b][h][l][dh]
__device__ float g_vproj[BB*H*L*DH];   // [b][h][l][dh]
__device__ float g_qlin[BL*D];         // raw q projection [m][d]
__device__ float g_w[BL*H*D];          // folded pos-weights [m][h][d], pre-scaled
__device__ float g_bias[BB*H*L];       // B_D bias term, pre-scaled
__device__ float g_score[BB*H*L*L];    // A_C+bias+mask, then attn  [z][q][k]

// ---------------- helpers ----------------
__device__ __forceinline__ void fma2(unsigned long long& acc, unsigned long long a, unsigned long long b) {
    asm("fma.rn.f32x2 %0, %1, %2, %0;" : "+l"(acc) : "l"(a), "l"(b));
}
__device__ __forceinline__ float hsum2(unsigned long long v) {
    return __uint_as_float((unsigned)v) + __uint_as_float((unsigned)(v >> 32));
}
__device__ __forceinline__ void cp16(unsigned saddr, const void* gptr) {
    asm volatile("cp.async.cg.shared.global [%0], [%1], 16;" :: "r"(saddr), "l"(gptr));
}

// ---------------- 1) QKV projections: [768,256] @ W^T + b ----------------
__global__ __launch_bounds__(256) void proj_kernel(
    const float* __restrict__ key, const float* __restrict__ query, const float* __restrict__ value,
    const float* __restrict__ Wk, const float* __restrict__ bk,
    const float* __restrict__ Wq, const float* __restrict__ bq,
    const float* __restrict__ Wv, const float* __restrict__ bv,
    const float* __restrict__ u)
{
    int op = blockIdx.z;
    const float* X = (op == 0) ? key : (op == 1) ? query : value;
    const float* W = (op == 0) ? Wk  : (op == 1) ? Wq    : Wv;
    const float* bs = (op == 0) ? bk : (op == 1) ? bq    : bv;
    int m0 = blockIdx.x * 64, n0 = blockIdx.y * 64;
    __shared__ float xs[64][36];
    __shared__ float ws[64][36];
    int t = threadIdx.x, tx = t & 15, ty = t >> 4;
    unsigned long long c2[4][4] = {};
    for (int k0 = 0; k0 < D; k0 += 32) {
        for (int f = t; f < 512; f += 256) {
            int row = f >> 3, c4 = (f & 7) * 4;
            *(float4*)&xs[row][c4] = *(const float4*)&X[(m0 + row) * D + k0 + c4];
            *(float4*)&ws[row][c4] = *(const float4*)&W[(n0 + row) * D + k0 + c4];
        }
        __syncthreads();
        #pragma unroll
        for (int kk = 0; kk < 32; kk += 4) {
            ulonglong2 a[4], b4[4];
            #pragma unroll
            for (int i = 0; i < 4; i++) a[i]  = *(ulonglong2*)&xs[ty*4+i][kk];
            #pragma unroll
            for (int j = 0; j < 4; j++) b4[j] = *(ulonglong2*)&ws[tx*4+j][kk];
            #pragma unroll
            for (int i = 0; i < 4; i++)
                #pragma unroll
                for (int j = 0; j < 4; j++) {
                    fma2(c2[i][j], a[i].x, b4[j].x);
                    fma2(c2[i][j], a[i].y, b4[j].y);
                }
        }
        __syncthreads();
    }
    #pragma unroll
    for (int i = 0; i < 4; i++) {
        int m = m0 + ty*4 + i, b = m / L, l = m % L;
        #pragma unroll
        for (int j = 0; j < 4; j++) {
            int n = n0 + tx*4 + j, h = n >> 5, dh = n & 31;
            float vout = hsum2(c2[i][j]) + bs[n];
            int idx = ((b*H + h)*L + l)*DH + dh;
            if (op == 0)      g_kproj[idx] = vout;
            else if (op == 2) g_vproj[idx] = vout;
            else {
                g_qlin[m*D + n] = vout;
                g_qu[idx] = (vout + u[n]) * INVS;
            }
        }
    }
}

// ---------------- 2) w fold: per head h, [768,32] @ Wr_h[32,256] ----------------
__global__ __launch_bounds__(256) void w_kernel(
    const float* __restrict__ Wr, const float* __restrict__ vpar)
{
    int h = blockIdx.z;
    int m0 = blockIdx.x * 64, n0 = blockIdx.y * 64;
    __shared__ float asT[32][68];   // transposed: [j][m-row]
    __shared__ float wrs[32][68];   // Wr[h*32+j][n]
    int t = threadIdx.x, tx = t & 15, ty = t >> 4;
    for (int f = t; f < 512; f += 256) {
        int row = f >> 3, c4 = (f & 7) * 4;
        float4 qv = *(const float4*)&g_qlin[(m0 + row)*D + h*DH + c4];
        float4 vv = *(const float4*)&vpar[h*DH + c4];
        asT[c4+0][row] = qv.x + vv.x;
        asT[c4+1][row] = qv.y + vv.y;
        asT[c4+2][row] = qv.z + vv.z;
        asT[c4+3][row] = qv.w + vv.w;
    }
    for (int f = t; f < 512; f += 256) {
        int row = f >> 4, c4 = (f & 15) * 4;
        *(float4*)&wrs[row][c4] = *(const float4*)&Wr[(h*DH + row)*D + n0 + c4];
    }
    __syncthreads();
    float c[4][4] = {};
    #pragma unroll
    for (int jj = 0; jj < 32; jj++) {
        float4 a4 = *(const float4*)&asT[jj][ty*4];
        float4 w4 = *(const float4*)&wrs[jj][tx*4];
        float ar[4] = {a4.x, a4.y, a4.z, a4.w};
        #pragma unroll
        for (int i = 0; i < 4; i++) {
            c[i][0] += ar[i]*w4.x; c[i][1] += ar[i]*w4.y;
            c[i][2] += ar[i]*w4.z; c[i][3] += ar[i]*w4.w;
        }
    }
    #pragma unroll
    for (int i = 0; i < 4; i++) {
        int m = m0 + ty*4 + i;
        float4 o = {c[i][0]*INVS, c[i][1]*INVS, c[i][2]*INVS, c[i][3]*INVS};
        *(float4*)&g_w[(m*H + h)*D + n0 + tx*4] = o;
    }
}

// ---------------- 2b) B_D bias ----------------
__global__ void bias_kernel(const float* __restrict__ vpar, const float* __restrict__ br) {
    int idx = blockIdx.x * blockDim.x + threadIdx.x;
    if (idx >= BL * H) return;
    int m = idx >> 3, h = idx & 7;
    float s = 0.f;
    for (int j = 0; j < DH; j++)
        s += (g_qlin[m*D + h*DH + j] + vpar[h*DH + j]) * br[h*DH + j];
    int b = m / L, l = m % L;
    g_bias[(b*H + h)*L + l] = s * INVS;
}

// ---------------- 3) content scores A_C (+bias +mask) ----------------
__global__ __launch_bounds__(256) void ac_kernel(const float* __restrict__ key_mask) {
    int z = blockIdx.z;            // b*H + h
    int b = z >> 3;
    int q0 = blockIdx.x * 64, k0 = blockIdx.y * 64;
    __shared__ float qsT[32][68], ksT[32][68];   // transposed [dh][row]
    int t = threadIdx.x, tx = t & 15, ty = t >> 4;
    for (int f = t; f < 512; f += 256) {
        int row = f >> 3, c4 = (f & 7) * 4;
        float4 qv = *(const float4*)&g_qu[(z*L + q0 + row)*DH + c4];
        float4 kv = *(const float4*)&g_kproj[(z*L + k0 + row)*DH + c4];
        qsT[c4+0][row] = qv.x; qsT[c4+1][row] = qv.y;
        qsT[c4+2][row] = qv.z; qsT[c4+3][row] = qv.w;
        ksT[c4+0][row] = kv.x; ksT[c4+1][row] = kv.y;
        ksT[c4+2][row] = kv.z; ksT[c4+3][row] = kv.w;
    }
    __syncthreads();
    float c[4][4] = {};
    #pragma unroll
    for (int kk = 0; kk < 32; kk++) {
        float4 a4 = *(const float4*)&qsT[kk][ty*4];
        float4 b4 = *(const float4*)&ksT[kk][tx*4];
        float ar[4] = {a4.x, a4.y, a4.z, a4.w};
        #pragma unroll
        for (int i = 0; i < 4; i++) {
            c[i][0] += ar[i]*b4.x; c[i][1] += ar[i]*b4.y;
            c[i][2] += ar[i]*b4.z; c[i][3] += ar[i]*b4.w;
        }
    }
    float msk[4];
    #pragma unroll
    for (int j = 0; j < 4; j++)
        msk[j] = (1.f - key_mask[b*L + k0 + tx*4 + j]) * 1e15f;
    #pragma unroll
    for (int i = 0; i < 4; i++) {
        int q = q0 + ty*4 + i;
        float bias = g_bias[z*L + q];
        float4 o;
        o.x = c[i][0] + bias - msk[0];
        o.y = c[i][1] + bias - msk[1];
        o.z = c[i][2] + bias - msk[2];
        o.w = c[i][3] + bias - msk[3];
        *(float4*)&g_score[((size_t)z*L + q)*L + k0 + tx*4] = o;
    }
}

// ---------------- 4) MAIN: persistent, cp.async-pipelined B_D + softmax ----------------
#define DCHUNK 64
#define PSTR 68          // 64 + 4 pad: conflict-free LDS.128 (8-lane groups)
#define NCHUNK 4         // D / DCHUNK
#define GRIDB 148        // one CTA per SM
extern __shared__ float smem3[];
__global__ __launch_bounds__(384, 1) void bd_softmax_kernel(const float* __restrict__ pos) {
    float* w_s  = smem3;                       // 2048 floats
    float* bufA = smem3 + 2048;                // 384*68 floats
    float* bufB = bufA + 384*PSTR;             // 384*68 floats
    __shared__ float red[16];
    int t = threadIdx.x;
    unsigned sA = (unsigned)__cvta_generic_to_shared(bufA);
    unsigned sB = (unsigned)__cvta_generic_to_shared(bufB);
    int row16 = t >> 4, c16 = (t & 15) << 2;   // fixed per-thread load slot

    // prologue: prefetch chunk 0 of first m into bufA
    {
        const float* src = pos + (size_t)blockIdx.x * (L*D);
        #pragma unroll
        for (int k = 0; k < 16; k++) {
            int row = row16 + k*24;
            cp16(sA + (unsigned)(row*PSTR + c16)*4u, src + row*D + c16);
        }
        asm volatile("cp.async.commit_group;");
    }

    for (int m = blockIdx.x; m < BL; m += GRIDB) {
        // w for this m + score row prefetch (registers, independent of pos stream)
        for (int j = t; j < H*D; j += 384) w_s[j] = g_w[(size_t)m*(H*D) + j];
        int bq = m / L, q = m - bq*L;
        float sc0[8];
        #pragma unroll
        for (int h = 0; h < 8; h++)
            sc0[h] = g_score[((size_t)(bq*H + h)*L + q)*L + t];

        unsigned long long accA[8] = {}, accB[8] = {};
        for (int c = 0; c < NCHUNK; c++) {
            if (c + 1 < NCHUNK) {
                const float* src = pos + (size_t)m*(L*D) + (c+1)*DCHUNK;
                unsigned sb = ((c+1) & 1) ? sB : sA;
                #pragma unroll
                for (int k = 0; k < 16; k++) {
                    int row = row16 + k*24;
                    cp16(sb + (unsigned)(row*PSTR + c16)*4u, src + row*D + c16);
                }
            } else if (m + GRIDB < BL) {
                const float* src = pos + (size_t)(m + GRIDB)*(L*D);
                #pragma unroll
                for (int k = 0; k < 16; k++) {
                    int row = row16 + k*24;
                    cp16(sA + (unsigned)(row*PSTR + c16)*4u, src + row*D + c16);
                }
            }
            asm volatile("cp.async.commit_group;");
            asm volatile("cp.async.wait_group 1;");   // current chunk's group done
            __syncthreads();

            const float* buf = (c & 1) ? bufB : bufA;
            const ulonglong2* myrow = (const ulonglong2*)(buf + t*PSTR);
            const float* wc = w_s + c*DCHUNK;
            #pragma unroll
            for (int d4 = 0; d4 < DCHUNK/4; d4++) {
                ulonglong2 p = myrow[d4];
                #pragma unroll
                for (int h = 0; h < 8; h++) {
                    ulonglong2 wv = *(const ulonglong2*)(wc + h*D + d4*4);
                    fma2(accA[h], p.x, wv.x);
                    fma2(accB[h], p.y, wv.y);
                }
            }
            __syncthreads();   // all reads of this buffer done before refill
        }

        // ----- softmax epilogue (sc_s lives in bufB; bufA is being refilled) -----
        float sc[8];
        #pragma unroll
        for (int h = 0; h < 8; h++)
            sc[h] = hsum2(accA[h]) + hsum2(accB[h]) + sc0[h];
        float* sc_s = bufB;   // 8*392 floats
        #pragma unroll
        for (int h = 0; h < 8; h++) sc_s[h*392 + t] = sc[h];
        __syncthreads();
        int wid = t >> 5, lane = t & 31;
        if (wid < 8) {
            float mx = -1e30f;
            for (int j = lane; j < L; j += 32) mx = fmaxf(mx, sc_s[wid*392 + j]);
            #pragma unroll
            for (int o = 16; o; o >>= 1) mx = fmaxf(mx, __shfl_xor_sync(0xffffffffu, mx, o));
            if (lane == 0) red[wid] = mx;
        }
        __syncthreads();
        float e[8];
        #pragma unroll
        for (int h = 0; h < 8; h++) { e[h] = __expf(sc[h] - red[h]); sc_s[h*392 + t] = e[h]; }
        __syncthreads();
        if (wid < 8) {
            float s = 0.f;
            for (int j = lane; j < L; j += 32) s += sc_s[wid*392 + j];
            #pragma unroll
            for (int o = 16; o; o >>= 1) s += __shfl_xor_sync(0xffffffffu, s, o);
            if (lane == 0) red[8 + wid] = 1.0f / s;
        }
        __syncthreads();
        #pragma unroll
        for (int h = 0; h < 8; h++)
            g_score[((size_t)(bq*H + h)*L + q)*L + t] = e[h] * red[8 + h];
        __syncthreads();   // sc_s (bufB) & w_s free before next m reuses them
    }
}

// ---------------- 5) out = attn @ V  (tiled smem GEMM) ----------------
#define OQT 24
#define OKT 96
__global__ __launch_bounds__(256) void out_kernel(float* __restrict__ out) {
    __shared__ float at_s[OQT][OKT+4];    // attn tile, rows broadcast-read
    __shared__ float vt_s[DH][OKT+4];     // V transposed: [dh][k]
    int z = blockIdx.x, b = z >> 3, h = z & 7;
    int q0 = blockIdx.y * OQT;
    int t = threadIdx.x, dh = t & 31, qg = t >> 5;   // qg in 0..7, 3 q's each
    unsigned long long acc2[3] = {};
    for (int k0 = 0; k0 < L; k0 += OKT) {
        __syncthreads();
        // attn tile: 24 x 96 floats = 576 float4
        for (int f = t; f < OQT*(OKT/4); f += 256) {
            int row = f / (OKT/4), c4 = (f % (OKT/4)) * 4;
            *(float4*)&at_s[row][c4] =
                *(const float4*)&g_score[((size_t)z*L + q0 + row)*L + k0 + c4];
        }
        // V tile transposed: coalesced gmem read
        for (int f = t; f < OKT*DH; f += 256) {
            int k = f >> 5, d = f & 31;
            vt_s[d][k] = g_vproj[((size_t)z*L + k0 + k)*DH + d];
        }
        __syncthreads();
        #pragma unroll
        for (int kk = 0; kk < OKT; kk += 4) {
            ulonglong2 v = *(const ulonglong2*)&vt_s[dh][kk];
            #pragma unroll
            for (int i = 0; i < 3; i++) {
                ulonglong2 a = *(const ulonglong2*)&at_s[qg*3 + i][kk];
                fma2(acc2[i], a.x, v.x);
                fma2(acc2[i], a.y, v.y);
            }
        }
    }
    #pragma unroll
    for (int i = 0; i < 3; i++) {
        int q = q0 + qg*3 + i;
        out[(size_t)(b*L + q)*D + h*DH + dh] = hsum2(acc2[i]);
    }
}

// ---------------- launch ----------------
extern "C" void kernel_launch(void* const* d_in, const int* in_sizes, int n_in,
                              void* d_out, int out_size) {
    const float* key      = (const float*)d_in[0];
    const float* query    = (const float*)d_in[1];
    const float* value    = (const float*)d_in[2];
    const float* pos      = (const float*)d_in[3];
    const float* key_mask = (const float*)d_in[4];
    const float* Wk = (const float*)d_in[5];  const float* bk = (const float*)d_in[6];
    const float* Wq = (const float*)d_in[7];  const float* bq = (const float*)d_in[8];
    const float* Wv = (const float*)d_in[9];  const float* bv = (const float*)d_in[10];
    const float* Wr = (const float*)d_in[11]; const float* br = (const float*)d_in[12];
    const float* u  = (const float*)d_in[13]; const float* vp = (const float*)d_in[14];
    float* out = (float*)d_out;

    // 2048 (w) + 2*384*68 (double buffer) floats = 217088 bytes
    cudaFuncSetAttribute(bd_softmax_kernel, cudaFuncAttributeMaxDynamicSharedMemorySize, 217088);

    proj_kernel<<<dim3(12, 4, 3), 256>>>(key, query, value, Wk, bk, Wq, bq, Wv, bv, u);
    w_kernel<<<dim3(12, 4, 8), 256>>>(Wr, vp);
    bias_kernel<<<24, 256>>>(vp, br);
    ac_kernel<<<dim3(6, 6, 16), 256>>>(key_mask);
    bd_softmax_kernel<<<GRIDB, 384, 217088>>>(pos);
    out_kernel<<<dim3(16, 16), 256>>>(out);
}

// round 6
// speedup vs baseline: 1.6290x; 1.6290x over previous
#include <cuda_runtime.h>

#define BB 2
#define L 384
#define D 256
#define H 8
#define DH 32
#define BL (BB*L)
#define INVS 0.17677669529663687f   // 1/sqrt(32)

// ---------------- scratch (static device globals; no allocations) ----------------
__device__ float g_kproj[BB*H*L*DH];   // [b][h][l][dh]
__device__ float g_qu[BB*H*L*DH];      // (q+u)*INVS, [b][h][l][dh]
__device__ float g_vproj[BB*H*L*DH];   // [b][h][l][dh]
__device__ float g_qlin[BL*D];         // raw q projection [m][d]
__device__ float g_w[BL*H*D];          // folded pos-weights [m][h][d], pre-scaled
__device__ float g_bias[BB*H*L];       // B_D bias term, pre-scaled
__device__ float g_score[BB*H*L*L];    // A_C+bias+mask, then attn  [z][q][k]

// ---------------- helpers ----------------
__device__ __forceinline__ void fma2(unsigned long long& acc, unsigned long long a, unsigned long long b) {
    asm("fma.rn.f32x2 %0, %1, %2, %0;" : "+l"(acc) : "l"(a), "l"(b));
}
__device__ __forceinline__ float hsum2(unsigned long long v) {
    return __uint_as_float((unsigned)v) + __uint_as_float((unsigned)(v >> 32));
}
__device__ __forceinline__ void cp16(unsigned saddr, const void* gptr) {
    asm volatile("cp.async.cg.shared.global [%0], [%1], 16;" :: "r"(saddr), "l"(gptr));
}

// ---------------- 1) QKV projections (ac-style: transposed smem, scalar acc) ----------------
__global__ __launch_bounds__(256) void proj_kernel(
    const float* __restrict__ key, const float* __restrict__ query, const float* __restrict__ value,
    const float* __restrict__ Wk, const float* __restrict__ bk,
    const float* __restrict__ Wq, const float* __restrict__ bq,
    const float* __restrict__ Wv, const float* __restrict__ bv,
    const float* __restrict__ u)
{
    int op = blockIdx.z;
    const float* X = (op == 0) ? key : (op == 1) ? query : value;
    const float* W = (op == 0) ? Wk  : (op == 1) ? Wq    : Wv;
    const float* bs = (op == 0) ? bk : (op == 1) ? bq    : bv;
    int m0 = blockIdx.x * 64, n0 = blockIdx.y * 64;
    __shared__ float xsT[32][68], wsT[32][68];   // transposed [k][row]
    int t = threadIdx.x, tx = t & 15, ty = t >> 4;
    float c[4][4] = {};
    for (int k0 = 0; k0 < D; k0 += 32) {
        __syncthreads();
        for (int f = t; f < 512; f += 256) {
            int row = f >> 3, c4 = (f & 7) * 4;
            float4 xv = *(const float4*)&X[(m0 + row)*D + k0 + c4];
            float4 wv = *(const float4*)&W[(n0 + row)*D + k0 + c4];
            xsT[c4+0][row] = xv.x; xsT[c4+1][row] = xv.y;
            xsT[c4+2][row] = xv.z; xsT[c4+3][row] = xv.w;
            wsT[c4+0][row] = wv.x; wsT[c4+1][row] = wv.y;
            wsT[c4+2][row] = wv.z; wsT[c4+3][row] = wv.w;
        }
        __syncthreads();
        #pragma unroll
        for (int kk = 0; kk < 32; kk++) {
            float4 a4 = *(const float4*)&xsT[kk][ty*4];
            float4 b4 = *(const float4*)&wsT[kk][tx*4];
            float ar[4] = {a4.x, a4.y, a4.z, a4.w};
            #pragma unroll
            for (int i = 0; i < 4; i++) {
                c[i][0] += ar[i]*b4.x; c[i][1] += ar[i]*b4.y;
                c[i][2] += ar[i]*b4.z; c[i][3] += ar[i]*b4.w;
            }
        }
    }
    int n = n0 + tx*4;                 // 4-aligned; h,dh constant over the float4
    int h = n >> 5, dh = n & 31;
    float4 bs4 = *(const float4*)&bs[n];
    #pragma unroll
    for (int i = 0; i < 4; i++) {
        int m = m0 + ty*4 + i, b = m / L, l = m % L;
        float4 o = {c[i][0]+bs4.x, c[i][1]+bs4.y, c[i][2]+bs4.z, c[i][3]+bs4.w};
        int idx = ((b*H + h)*L + l)*DH + dh;
        if (op == 0)      *(float4*)&g_kproj[idx] = o;
        else if (op == 2) *(float4*)&g_vproj[idx] = o;
        else {
            *(float4*)&g_qlin[m*D + n] = o;
            float4 u4 = *(const float4*)&u[n];
            float4 q = {(o.x+u4.x)*INVS, (o.y+u4.y)*INVS, (o.z+u4.z)*INVS, (o.w+u4.w)*INVS};
            *(float4*)&g_qu[idx] = q;
        }
    }
}

// ---------------- 2) fused setup: ac (blocks 0..575) | w (576..959) | bias (960..983) ----------------
__global__ __launch_bounds__(256) void setup_kernel(
    const float* __restrict__ key_mask,
    const float* __restrict__ Wr, const float* __restrict__ vpar,
    const float* __restrict__ br)
{
    __shared__ float sh0[32][68], sh1[32][68];
    int bz = blockIdx.x;
    int t = threadIdx.x, tx = t & 15, ty = t >> 4;

    if (bz < 576) {
        // ---- content scores A_C (+bias +mask) ----
        int idx = bz;
        int z = idx & 15;                 // b*H + h
        int rr = idx >> 4;
        int q0 = (rr % 6) * 64, k0 = (rr / 6) * 64;
        int b = z >> 3;
        for (int f = t; f < 512; f += 256) {
            int row = f >> 3, c4 = (f & 7) * 4;
            float4 qv = *(const float4*)&g_qu[(z*L + q0 + row)*DH + c4];
            float4 kv = *(const float4*)&g_kproj[(z*L + k0 + row)*DH + c4];
            sh0[c4+0][row] = qv.x; sh0[c4+1][row] = qv.y;
            sh0[c4+2][row] = qv.z; sh0[c4+3][row] = qv.w;
            sh1[c4+0][row] = kv.x; sh1[c4+1][row] = kv.y;
            sh1[c4+2][row] = kv.z; sh1[c4+3][row] = kv.w;
        }
        __syncthreads();
        float c[4][4] = {};
        #pragma unroll
        for (int kk = 0; kk < 32; kk++) {
            float4 a4 = *(const float4*)&sh0[kk][ty*4];
            float4 b4 = *(const float4*)&sh1[kk][tx*4];
            float ar[4] = {a4.x, a4.y, a4.z, a4.w};
            #pragma unroll
            for (int i = 0; i < 4; i++) {
                c[i][0] += ar[i]*b4.x; c[i][1] += ar[i]*b4.y;
                c[i][2] += ar[i]*b4.z; c[i][3] += ar[i]*b4.w;
            }
        }
        float msk[4];
        #pragma unroll
        for (int j = 0; j < 4; j++)
            msk[j] = (1.f - key_mask[b*L + k0 + tx*4 + j]) * 1e15f;
        #pragma unroll
        for (int i = 0; i < 4; i++) {
            int q = q0 + ty*4 + i;
            float bias = g_bias[z*L + q];
            float4 o;
            o.x = c[i][0] + bias - msk[0];
            o.y = c[i][1] + bias - msk[1];
            o.z = c[i][2] + bias - msk[2];
            o.w = c[i][3] + bias - msk[3];
            *(float4*)&g_score[((size_t)z*L + q)*L + k0 + tx*4] = o;
        }
    } else if (bz < 960) {
        // ---- w fold: per head h, [768,32] @ Wr_h[32,256] ----
        int idx = bz - 576;
        int h = idx & 7;
        int rr = idx >> 3;
        int m0 = (rr % 12) * 64, n0 = (rr / 12) * 64;
        for (int f = t; f < 512; f += 256) {
            int row = f >> 3, c4 = (f & 7) * 4;
            float4 qv = *(const float4*)&g_qlin[(m0 + row)*D + h*DH + c4];
            float4 vv = *(const float4*)&vpar[h*DH + c4];
            sh0[c4+0][row] = qv.x + vv.x;
            sh0[c4+1][row] = qv.y + vv.y;
            sh0[c4+2][row] = qv.z + vv.z;
            sh0[c4+3][row] = qv.w + vv.w;
        }
        for (int f = t; f < 512; f += 256) {
            int row = f >> 4, c4 = (f & 15) * 4;
            *(float4*)&sh1[row][c4] = *(const float4*)&Wr[(h*DH + row)*D + n0 + c4];
        }
        __syncthreads();
        float c[4][4] = {};
        #pragma unroll
        for (int jj = 0; jj < 32; jj++) {
            float4 a4 = *(const float4*)&sh0[jj][ty*4];
            float4 w4 = *(const float4*)&sh1[jj][tx*4];
            float ar[4] = {a4.x, a4.y, a4.z, a4.w};
            #pragma unroll
            for (int i = 0; i < 4; i++) {
                c[i][0] += ar[i]*w4.x; c[i][1] += ar[i]*w4.y;
                c[i][2] += ar[i]*w4.z; c[i][3] += ar[i]*w4.w;
            }
        }
        #pragma unroll
        for (int i = 0; i < 4; i++) {
            int m = m0 + ty*4 + i;
            float4 o = {c[i][0]*INVS, c[i][1]*INVS, c[i][2]*INVS, c[i][3]*INVS};
            *(float4*)&g_w[(m*H + h)*D + n0 + tx*4] = o;
        }
    } else {
        // ---- B_D bias ----
        int idx = (bz - 960) * 256 + t;
        int m = idx >> 3, h = idx & 7;
        float s = 0.f;
        for (int j = 0; j < DH; j++)
            s += (g_qlin[m*D + h*DH + j] + vpar[h*DH + j]) * br[h*DH + j];
        int b = m / L, l = m % L;
        g_bias[(b*H + h)*L + l] = s * INVS;
    }
}

// ---------------- 3) MAIN: persistent, cp.async-pipelined B_D + softmax (R4 structure) ----------------
#define DCHUNK 64
#define PSTR 68          // 64 + 4 pad: conflict-free LDS.128 (8-lane groups)
#define NCHUNK 4         // D / DCHUNK
#define MPB 6            // m's per block; 128 * 6 = 768
extern __shared__ float smem3[];
__global__ __launch_bounds__(384, 1) void bd_softmax_kernel(const float* __restrict__ pos) {
    float* w_s  = smem3;                       // 2048 floats
    float* bufA = smem3 + 2048;                // 384*68 floats
    float* bufB = bufA + 384*PSTR;             // 384*68 floats
    __shared__ float red[16];
    int t = threadIdx.x;
    int m0 = blockIdx.x * MPB;
    unsigned sA = (unsigned)__cvta_generic_to_shared(bufA);
    unsigned sB = (unsigned)__cvta_generic_to_shared(bufB);

    // prologue: prefetch chunk 0 of m0 into bufA
    {
        const float* src = pos + (size_t)m0 * (L*D);
        #pragma unroll
        for (int k = 0; k < 16; k++) {
            int f = t + k*384;
            int row = f >> 4, c4 = (f & 15) << 2;
            cp16(sA + (unsigned)(row*PSTR + c4)*4u, src + row*D + c4);
        }
        asm volatile("cp.async.commit_group;");
    }

    for (int i = 0; i < MPB; i++) {
        int m = m0 + i;
        // w for this m (float4) + score row prefetch into registers
        for (int j = t; j < 512; j += 384)
            *(float4*)&w_s[j*4] = *(const float4*)&g_w[(size_t)m*(H*D) + j*4];
        int bq = m / L, q = m - bq*L;
        float sc0[8];
        #pragma unroll
        for (int h = 0; h < 8; h++)
            sc0[h] = g_score[((size_t)(bq*H + h)*L + q)*L + t];

        unsigned long long accA[8] = {}, accB[8] = {};
        for (int c = 0; c < NCHUNK; c++) {
            if (c + 1 < NCHUNK) {
                const float* src = pos + (size_t)m*(L*D) + (c+1)*DCHUNK;
                unsigned sb = ((c+1) & 1) ? sB : sA;
                #pragma unroll
                for (int k = 0; k < 16; k++) {
                    int f = t + k*384;
                    int row = f >> 4, c4 = (f & 15) << 2;
                    cp16(sb + (unsigned)(row*PSTR + c4)*4u, src + row*D + c4);
                }
            } else if (i + 1 < MPB) {
                const float* src = pos + (size_t)(m+1)*(L*D);
                #pragma unroll
                for (int k = 0; k < 16; k++) {
                    int f = t + k*384;
                    int row = f >> 4, c4 = (f & 15) << 2;
                    cp16(sA + (unsigned)(row*PSTR + c4)*4u, src + row*D + c4);
                }
            }
            asm volatile("cp.async.commit_group;");
            asm volatile("cp.async.wait_group 1;");   // current chunk's group done
            __syncthreads();

            const float* buf = (c & 1) ? bufB : bufA;
            const ulonglong2* myrow = (const ulonglong2*)(buf + t*PSTR);
            const float* wc = w_s + c*DCHUNK;
            #pragma unroll
            for (int d4 = 0; d4 < DCHUNK/4; d4++) {
                ulonglong2 p = myrow[d4];
                #pragma unroll
                for (int h = 0; h < 8; h++) {
                    ulonglong2 wv = *(const ulonglong2*)(wc + h*D + d4*4);
                    fma2(accA[h], p.x, wv.x);
                    fma2(accB[h], p.y, wv.y);
                }
            }
            __syncthreads();   // all reads of this buffer done before refill
        }

        // ----- softmax epilogue (sc_s lives in bufB; bufA is being refilled) -----
        float sc[8];
        #pragma unroll
        for (int h = 0; h < 8; h++)
            sc[h] = hsum2(accA[h]) + hsum2(accB[h]) + sc0[h];
        float* sc_s = bufB;   // 8*392 floats
        #pragma unroll
        for (int h = 0; h < 8; h++) sc_s[h*392 + t] = sc[h];
        __syncthreads();
        int wid = t >> 5, lane = t & 31;
        if (wid < 8) {
            float mx = -1e30f;
            for (int j = lane; j < L; j += 32) mx = fmaxf(mx, sc_s[wid*392 + j]);
            #pragma unroll
            for (int o = 16; o; o >>= 1) mx = fmaxf(mx, __shfl_xor_sync(0xffffffffu, mx, o));
            if (lane == 0) red[wid] = mx;
        }
        __syncthreads();
        float e[8];
        #pragma unroll
        for (int h = 0; h < 8; h++) { e[h] = __expf(sc[h] - red[h]); sc_s[h*392 + t] = e[h]; }
        __syncthreads();
        if (wid < 8) {
            float s = 0.f;
            for (int j = lane; j < L; j += 32) s += sc_s[wid*392 + j];
            #pragma unroll
            for (int o = 16; o; o >>= 1) s += __shfl_xor_sync(0xffffffffu, s, o);
            if (lane == 0) red[8 + wid] = 1.0f / s;
        }
        __syncthreads();
        #pragma unroll
        for (int h = 0; h < 8; h++)
            g_score[((size_t)(bq*H + h)*L + q)*L + t] = e[h] * red[8 + h];
        __syncthreads();   // sc_s (bufB) & w_s free before next m reuses them
    }
}

// ---------------- 4) out = attn @ V  (tiled smem GEMM, R4 config) ----------------
#define OQT 48
#define OKT 96
__global__ __launch_bounds__(256) void out_kernel(float* __restrict__ out) {
    __shared__ float at_s[OQT][OKT+4];    // attn tile, rows broadcast-read
    __shared__ float vt_s[DH][OKT+4];     // V transposed: [dh][k]
    int z = blockIdx.x, b = z >> 3, h = z & 7;
    int q0 = blockIdx.y * OQT;
    int t = threadIdx.x, dh = t & 31, qg = t >> 5;   // qg in 0..7, 6 q's each
    unsigned long long acc2[6] = {};
    for (int k0 = 0; k0 < L; k0 += OKT) {
        __syncthreads();
        for (int f = t; f < OQT*(OKT/4); f += 256) {
            int row = f / (OKT/4), c4 = (f % (OKT/4)) * 4;
            *(float4*)&at_s[row][c4] =
                *(const float4*)&g_score[((size_t)z*L + q0 + row)*L + k0 + c4];
        }
        for (int f = t; f < OKT*DH; f += 256) {
            int k = f >> 5, d = f & 31;
            vt_s[d][k] = g_vproj[((size_t)z*L + k0 + k)*DH + d];
        }
        __syncthreads();
        #pragma unroll
        for (int kk = 0; kk < OKT; kk += 4) {
            ulonglong2 v = *(const ulonglong2*)&vt_s[dh][kk];
            #pragma unroll
            for (int i = 0; i < 6; i++) {
                ulonglong2 a = *(const ulonglong2*)&at_s[qg*6 + i][kk];
                fma2(acc2[i], a.x, v.x);
                fma2(acc2[i], a.y, v.y);
            }
        }
    }
    #pragma unroll
    for (int i = 0; i < 6; i++) {
        int q = q0 + qg*6 + i;
        out[(size_t)(b*L + q)*D + h*DH + dh] = hsum2(acc2[i]);
    }
}

// ---------------- launch ----------------
extern "C" void kernel_launch(void* const* d_in, const int* in_sizes, int n_in,
                              void* d_out, int out_size) {
    const float* key      = (const float*)d_in[0];
    const float* query    = (const float*)d_in[1];
    const float* value    = (const float*)d_in[2];
    const float* pos      = (const float*)d_in[3];
    const float* key_mask = (const float*)d_in[4];
    const float* Wk = (const float*)d_in[5];  const float* bk = (const float*)d_in[6];
    const float* Wq = (const float*)d_in[7];  const float* bq = (const float*)d_in[8];
    const float* Wv = (const float*)d_in[9];  const float* bv = (const float*)d_in[10];
    const float* Wr = (const float*)d_in[11]; const float* br = (const float*)d_in[12];
    const float* u  = (const float*)d_in[13]; const float* vp = (const float*)d_in[14];
    float* out = (float*)d_out;

    // 2048 (w) + 2*384*68 (double buffer) floats = 217088 bytes
    cudaFuncSetAttribute(bd_softmax_kernel, cudaFuncAttributeMaxDynamicSharedMemorySize, 217088);

    proj_kernel<<<dim3(12, 4, 3), 256>>>(key, query, value, Wk, bk, Wq, bq, Wv, bv, u);
    setup_kernel<<<984, 256>>>(key_mask, Wr, vp, br);
    bd_softmax_kernel<<<128, 384, 217088>>>(pos);
    out_kernel<<<dim3(16, 8), 256>>>(out);
}